// round 5
// baseline (speedup 1.0000x reference)
#include <cuda_runtime.h>

#define Nn 100000
#define Gg 1000
#define Ee 1600000
#define EGe 16000
#define SCAN_BS 512
#define NB1 ((Nn + SCAN_BS - 1) / SCAN_BS)

// ---------------- scratch (device globals; no runtime allocation) ----------------
static __device__ __align__(16) float g_h1[Nn*128];     // x @ W1
static __device__ __align__(16) float g_asrc1[Nn*4];
static __device__ __align__(16) float g_adst1[Nn*4];
static __device__ __align__(16) float g_h2[Gg*128];
static __device__ __align__(16) float g_xgf[Gg*128];    // GAT2 final (with bias2)
static __device__ __align__(16) float g_adj[Gg*128];    // adjacent-group mean
static __device__ __align__(16) float g_asrc2[Gg*4];
static __device__ __align__(16) float g_adst2[Gg*4];
static __device__ float g_cnt[Gg];

// CSR scratch
static __device__ int g_deg1[Nn];
static __device__ int g_row1[Nn + 1];
static __device__ int g_cur1[Nn];
static __device__ int g_csr1[Ee + Nn];
static __device__ int g_bsum1[NB1];
static __device__ int g_row2[Gg + 1];
static __device__ int g_csr2[EGe + Gg];

__device__ __forceinline__ void redAddV4(float* p, float a, float b, float c, float d) {
    asm volatile("red.global.add.v4.f32 [%0], {%1, %2, %3, %4};"
                 :: "l"(p), "f"(a), "f"(b), "f"(c), "f"(d) : "memory");
}
__device__ __forceinline__ unsigned long long pk2(float x) {
    unsigned long long r;
    asm("mov.b64 %0, {%1, %1};" : "=l"(r) : "f"(x));
    return r;
}
#define FMA2(acc, a, b) asm("fma.rn.f32x2 %0, %1, %2, %0;" : "+l"(acc) : "l"(a), "l"(b))
__device__ __forceinline__ void unpk2(unsigned long long v, float& lo, float& hi) {
    asm("mov.b64 {%0, %1}, %2;" : "=f"(lo), "=f"(hi) : "l"(v));
}

// ---------------- init: covers Gg*128 = 128000 > Nn ----------------
__global__ void init_kernel() {
    int i = blockIdx.x * blockDim.x + threadIdx.x;
    if (i < Nn) g_deg1[i] = 1;            // self-loop baked into degree
    if (i < Gg*128) g_adj[i] = 0.f;
    if (i < Gg) g_cnt[i] = 0.f;
}

// ---------------- graph-1 CSR build ----------------
__global__ void hist_kernel(const int* __restrict__ dst) {
    int e = blockIdx.x * blockDim.x + threadIdx.x;
    if (e < Ee) atomicAdd(&g_deg1[dst[e]], 1);
}

__global__ void scan1_kernel() {
    __shared__ int s[SCAN_BS];
    int tid = threadIdx.x;
    int i = blockIdx.x * SCAN_BS + tid;
    int v = (i < Nn) ? g_deg1[i] : 0;
    s[tid] = v;
    __syncthreads();
    #pragma unroll
    for (int off = 1; off < SCAN_BS; off <<= 1) {
        int t = (tid >= off) ? s[tid - off] : 0;
        __syncthreads();
        s[tid] += t;
        __syncthreads();
    }
    if (i < Nn) g_row1[i] = s[tid] - v;   // exclusive (within block)
    if (tid == SCAN_BS - 1) g_bsum1[blockIdx.x] = s[tid];
}

__global__ void scan2_kernel() {
    __shared__ int s[256];
    int tid = threadIdx.x;
    int v = (tid < NB1) ? g_bsum1[tid] : 0;
    s[tid] = v;
    __syncthreads();
    #pragma unroll
    for (int off = 1; off < 256; off <<= 1) {
        int t = (tid >= off) ? s[tid - off] : 0;
        __syncthreads();
        s[tid] += t;
        __syncthreads();
    }
    if (tid < NB1) g_bsum1[tid] = s[tid] - v;  // exclusive
}

__global__ void scan3_kernel() {
    int i = blockIdx.x * SCAN_BS + threadIdx.x;
    if (i < Nn) {
        int r = g_row1[i] + g_bsum1[blockIdx.x];
        g_row1[i] = r;
        g_cur1[i] = r;
    }
    if (i == 0) g_row1[Nn] = Ee + Nn;
}

__global__ void scatter_kernel(const int* __restrict__ src, const int* __restrict__ dst) {
    int e = blockIdx.x * blockDim.x + threadIdx.x;
    if (e >= Ee + Nn) return;
    int si, di;
    if (e < Ee) { si = src[e]; di = dst[e]; } else { si = di = e - Ee; }
    int pos = atomicAdd(&g_cur1[di], 1);
    g_csr1[pos] = si;
}

// ---------------- graph-2 CSR build: one block, smem hist+scan+scatter ----------------
__global__ void build_csr2_kernel(const int* __restrict__ eig) {
    __shared__ int sdeg[1024];
    __shared__ int sscan[1024];
    __shared__ int scur[Gg];
    int t = threadIdx.x;
    sdeg[t] = (t < Gg) ? 1 : 0;            // self-loop
    __syncthreads();
    for (int e = t; e < EGe; e += 1024) atomicAdd(&sdeg[eig[EGe + e]], 1);
    __syncthreads();
    int v = sdeg[t];
    sscan[t] = v;
    __syncthreads();
    #pragma unroll
    for (int off = 1; off < 1024; off <<= 1) {
        int tv = (t >= off) ? sscan[t - off] : 0;
        __syncthreads();
        sscan[t] += tv;
        __syncthreads();
    }
    int excl = sscan[t] - v;
    if (t < Gg) { g_row2[t] = excl; scur[t] = excl; }
    if (t == 0) g_row2[Gg] = EGe + Gg;
    __syncthreads();
    for (int e = t; e < EGe + Gg; e += 1024) {
        int si, di;
        if (e < EGe) { si = eig[e]; di = eig[EGe + e]; } else { si = di = e - EGe; }
        int pos = atomicAdd(&scur[di], 1);
        g_csr2[pos] = si;
    }
}

// ---------------- GEMM (f32x2 packed FFMA): C[n,128] = A @ B, fused att scores ----
__global__ void gemm_k128(const float* __restrict__ A, const float* __restrict__ B,
                          const float* __restrict__ att_s, const float* __restrict__ att_d,
                          int which, int n) {
    float* C   = which ? g_h2 : g_h1;
    float* as_ = which ? g_asrc2 : g_asrc1;
    float* ad_ = which ? g_adst2 : g_adst1;
    __shared__ float As[16][68];   // [k][row], padded; rows contiguous -> f32x2 pairs
    __shared__ float Bs[16][128];  // [k][col]
    int t = threadIdx.x;
    int rowBase = blockIdx.x * 64;
    int tr = t >> 5, tc = t & 31;
    unsigned long long accP[4][4];   // [rowpair][col] : (row 2p, row 2p+1)
    #pragma unroll
    for (int p = 0; p < 4; p++)
        #pragma unroll
        for (int j = 0; j < 4; j++) accP[p][j] = 0ULL;

    for (int kt = 0; kt < 128; kt += 16) {
        int ar = t >> 2;
        int ac = (t & 3) << 2;
        int row = rowBase + ar;
        float4 av = (row < n) ? *(const float4*)(A + row*128 + kt + ac)
                              : make_float4(0.f, 0.f, 0.f, 0.f);
        As[ac+0][ar] = av.x; As[ac+1][ar] = av.y;
        As[ac+2][ar] = av.z; As[ac+3][ar] = av.w;
        int br = t >> 4;
        int bc = (t & 15) << 3;
        float4 b0 = *(const float4*)(B + (kt + br)*128 + bc);
        float4 b1 = *(const float4*)(B + (kt + br)*128 + bc + 4);
        *(float4*)&Bs[br][bc]     = b0;
        *(float4*)&Bs[br][bc + 4] = b1;
        __syncthreads();
        #pragma unroll
        for (int kk = 0; kk < 16; kk++) {
            ulonglong2 A01 = *(const ulonglong2*)&As[kk][tr*8];     // rows (0,1),(2,3)
            ulonglong2 A23 = *(const ulonglong2*)&As[kk][tr*8 + 4]; // rows (4,5),(6,7)
            float4 b = *(const float4*)&Bs[kk][tc*4];
            unsigned long long bb0 = pk2(b.x), bb1 = pk2(b.y), bb2 = pk2(b.z), bb3 = pk2(b.w);
            FMA2(accP[0][0], A01.x, bb0); FMA2(accP[0][1], A01.x, bb1);
            FMA2(accP[0][2], A01.x, bb2); FMA2(accP[0][3], A01.x, bb3);
            FMA2(accP[1][0], A01.y, bb0); FMA2(accP[1][1], A01.y, bb1);
            FMA2(accP[1][2], A01.y, bb2); FMA2(accP[1][3], A01.y, bb3);
            FMA2(accP[2][0], A23.x, bb0); FMA2(accP[2][1], A23.x, bb1);
            FMA2(accP[2][2], A23.x, bb2); FMA2(accP[2][3], A23.x, bb3);
            FMA2(accP[3][0], A23.y, bb0); FMA2(accP[3][1], A23.y, bb1);
            FMA2(accP[3][2], A23.y, bb2); FMA2(accP[3][3], A23.y, bb3);
        }
        __syncthreads();
    }
    float accv[8][4];
    #pragma unroll
    for (int p = 0; p < 4; p++)
        #pragma unroll
        for (int j = 0; j < 4; j++)
            unpk2(accP[p][j], accv[2*p][j], accv[2*p+1][j]);

    float4 sa = *(const float4*)(att_s + tc*4);
    float4 da = *(const float4*)(att_d + tc*4);
    int head = tc >> 3;
    #pragma unroll
    for (int i = 0; i < 8; i++) {
        int row = rowBase + tr*8 + i;
        if (row < n) {
            *(float4*)(C + row*128 + tc*4) =
                make_float4(accv[i][0], accv[i][1], accv[i][2], accv[i][3]);
            float ps = accv[i][0]*sa.x + accv[i][1]*sa.y + accv[i][2]*sa.z + accv[i][3]*sa.w;
            float pd = accv[i][0]*da.x + accv[i][1]*da.y + accv[i][2]*da.z + accv[i][3]*da.w;
            #pragma unroll
            for (int off = 4; off >= 1; off >>= 1) {
                ps += __shfl_xor_sync(0xffffffffu, ps, off);
                pd += __shfl_xor_sync(0xffffffffu, pd, off);
            }
            if ((tc & 7) == 0) {
                as_[row*4 + head] = ps;
                ad_[row*4 + head] = pd;
            }
        }
    }
}

// ---------------- graph-2: fused softmax + aggregation + bias2, writes xgf & d_out tail ----
__global__ void csr_agg2_kernel(const float* __restrict__ bias2, float* __restrict__ dtail) {
    int gid = blockIdx.x * blockDim.x + threadIdx.x;
    int d = gid >> 5, lane = threadIdx.x & 31;
    if (d >= Gg) return;
    int start = g_row2[d], end = g_row2[d + 1];
    int hd = lane >> 3;
    float adv = __ldg(&g_adst2[d*4 + hd]);
    float4 acc = make_float4(0.f, 0.f, 0.f, 0.f);
    float wsum = 0.f;
    int si = __ldg(&g_csr2[start]);
    for (int j = start; j < end; j++) {
        int sn = (j + 1 < end) ? __ldg(&g_csr2[j + 1]) : 0;
        float a = __ldg(&g_asrc2[si*4 + hd]);
        float4 hv = *(const float4*)(g_h2 + si*128 + lane*4);
        float e = a + adv;
        e = e > 0.f ? e : 0.2f*e;
        float w = __expf(e);
        acc.x += w*hv.x; acc.y += w*hv.y; acc.z += w*hv.z; acc.w += w*hv.w;
        wsum += w;
        si = sn;
    }
    float inv = 1.f / (wsum + 1e-16f);
    float4 bv = *(const float4*)(bias2 + lane*4);
    float4 r = make_float4(acc.x*inv + bv.x, acc.y*inv + bv.y,
                           acc.z*inv + bv.z, acc.w*inv + bv.w);
    *(float4*)(g_xgf + d*128 + lane*4) = r;
    *(float4*)(dtail + d*128 + lane*4) = r;
}

// ---------------- adjacency mean over group edges ----------------
__global__ void adj_accum_kernel(const int* __restrict__ eg) {
    int gid = blockIdx.x * blockDim.x + threadIdx.x;
    int w = gid >> 5, lane = threadIdx.x & 31;
    if (w >= EGe) return;
    int a = eg[w];         // edge_index_g[0]
    int b = eg[EGe + w];   // edge_index_g[1]
    float4 v = *(const float4*)(g_xgf + b*128 + lane*4);
    redAddV4(g_adj + a*128 + lane*4, v.x, v.y, v.z, v.w);
    if (lane == 0) atomicAdd(&g_cnt[a], 1.f);
}

__global__ void adj_mean_kernel() {
    int i = blockIdx.x * blockDim.x + threadIdx.x;
    if (i < Gg*128) g_adj[i] = g_adj[i] / fmaxf(g_cnt[i >> 7], 1.f);
}

// ---------------- graph-1: fused agg + bias + bilinear + FC(128->32) ----------------
// 256 threads, 16 nodes/block (Nn % 16 == 0 -> 6250 full blocks).
// Phase A: warp computes 2 nodes' u rows -> Us.  Phase B: register-cached W_fc GEMV.
__global__ void csr_agg_final_kernel(const float* __restrict__ bias1,
                                     const int* __restrict__ node_group,
                                     const float* __restrict__ Wfc,
                                     const float* __restrict__ bfc,
                                     float* __restrict__ out) {
    __shared__ float Ws[128*32];
    __shared__ float Us[16][128];
    int t = threadIdx.x;
    for (int i = t; i < 128*32; i += 256) Ws[i] = Wfc[i];
    __syncthreads();
    int o_col = t >> 3;      // 0..31 output column
    int seg   = t & 7;       // 0..7  K-segment of 16
    float wreg[16];
    #pragma unroll
    for (int i = 0; i < 16; i++) wreg[i] = Ws[(seg*16 + i)*32 + o_col];

    int w = t >> 5, lane = t & 31;
    int hd = lane >> 3;
    float4 b1 = *(const float4*)(bias1 + lane*4);

    #pragma unroll
    for (int jj = 0; jj < 2; jj++) {
        int d = blockIdx.x*16 + w*2 + jj;
        int start = g_row1[d], end = g_row1[d + 1];
        float adv = __ldg(&g_adst1[d*4 + hd]);
        float4 acc = make_float4(0.f, 0.f, 0.f, 0.f);
        float wsum = 0.f;
        int si = __ldg(&g_csr1[start]);
        for (int j = start; j < end; j++) {
            int sn = (j + 1 < end) ? __ldg(&g_csr1[j + 1]) : 0;
            float a = __ldg(&g_asrc1[si*4 + hd]);
            float4 hv = *(const float4*)(g_h1 + si*128 + lane*4);
            float e = a + adv;
            e = e > 0.f ? e : 0.2f*e;
            float wt = __expf(e);
            acc.x += wt*hv.x; acc.y += wt*hv.y; acc.z += wt*hv.z; acc.w += wt*hv.w;
            wsum += wt;
            si = sn;
        }
        float inv = 1.f / (wsum + 1e-16f);
        float4 xo = make_float4(acc.x*inv + b1.x, acc.y*inv + b1.y,
                                acc.z*inv + b1.z, acc.w*inv + b1.w);
        int g = __ldg(&node_group[d]);
        float4 gf = *(const float4*)(g_xgf + g*128 + lane*4);
        float4 af = *(const float4*)(g_adj + g*128 + lane*4);
        float pg = xo.x*gf.x + xo.y*gf.y + xo.z*gf.z + xo.w*gf.w;
        float pa = xo.x*af.x + xo.y*af.y + xo.z*af.z + xo.w*af.w;
        #pragma unroll
        for (int off = 16; off >= 1; off >>= 1) {
            pg += __shfl_xor_sync(0xffffffffu, pg, off);
            pa += __shfl_xor_sync(0xffffffffu, pa, off);
        }
        float4 u;
        u.x = xo.x + pg*gf.x + pa*af.x;
        u.y = xo.y + pg*gf.y + pa*af.y;
        u.z = xo.z + pg*gf.z + pa*af.z;
        u.w = xo.w + pg*gf.w + pa*af.w;
        *(float4*)&Us[w*2 + jj][lane*4] = u;
    }
    __syncthreads();

    float bfv = bfc[o_col];
    int nodeBase = blockIdx.x*16;
    #pragma unroll 4
    for (int nd = 0; nd < 16; nd++) {
        const float* ur = &Us[nd][seg*16];
        float4 u0 = *(const float4*)(ur);
        float4 u1 = *(const float4*)(ur + 4);
        float4 u2 = *(const float4*)(ur + 8);
        float4 u3 = *(const float4*)(ur + 12);
        float p = u0.x*wreg[0]  + u0.y*wreg[1]  + u0.z*wreg[2]  + u0.w*wreg[3]
                + u1.x*wreg[4]  + u1.y*wreg[5]  + u1.z*wreg[6]  + u1.w*wreg[7]
                + u2.x*wreg[8]  + u2.y*wreg[9]  + u2.z*wreg[10] + u2.w*wreg[11]
                + u3.x*wreg[12] + u3.y*wreg[13] + u3.z*wreg[14] + u3.w*wreg[15];
        p += __shfl_xor_sync(0xffffffffu, p, 1);
        p += __shfl_xor_sync(0xffffffffu, p, 2);
        p += __shfl_xor_sync(0xffffffffu, p, 4);
        if (seg == 0) out[(nodeBase + nd)*32 + o_col] = p + bfv;
    }
}

// ---------------- launch ----------------
extern "C" void kernel_launch(void* const* d_in, const int* in_sizes, int n_in,
                              void* d_out, int out_size) {
    const float* x    = (const float*)d_in[0];
    const float* x_g  = (const float*)d_in[1];
    const int*   ei   = (const int*)d_in[2];
    const int*   eig  = (const int*)d_in[3];
    const int*   ngrp = (const int*)d_in[4];
    const float* W1   = (const float*)d_in[5];
    const float* as1  = (const float*)d_in[6];
    const float* ad1  = (const float*)d_in[7];
    const float* b1   = (const float*)d_in[8];
    const float* W2   = (const float*)d_in[9];
    const float* as2  = (const float*)d_in[10];
    const float* ad2  = (const float*)d_in[11];
    const float* b2   = (const float*)d_in[12];
    const float* Wfc  = (const float*)d_in[13];
    const float* bfc  = (const float*)d_in[14];
    float* out = (float*)d_out;

    init_kernel<<<(Gg*128 + 255)/256, 256>>>();

    // CSR builds
    hist_kernel<<<(Ee + 255)/256, 256>>>(ei + Ee);
    scan1_kernel<<<NB1, SCAN_BS>>>();
    scan2_kernel<<<1, 256>>>();
    scan3_kernel<<<NB1, SCAN_BS>>>();
    scatter_kernel<<<(Ee + Nn + 255)/256, 256>>>(ei, ei + Ee);
    build_csr2_kernel<<<1, 1024>>>(eig);

    // group-graph chain (small)
    gemm_k128<<<(Gg + 63)/64, 256>>>(x_g, W2, as2, ad2, 1, Gg);
    csr_agg2_kernel<<<(Gg*32 + 255)/256, 256>>>(b2, out + Nn*32);
    adj_accum_kernel<<<(EGe*32 + 255)/256, 256>>>(eig);
    adj_mean_kernel<<<(Gg*128 + 255)/256, 256>>>();

    // big-graph chain
    gemm_k128<<<(Nn + 63)/64, 256>>>(x, W1, as1, ad1, 0, Nn);
    csr_agg_final_kernel<<<Nn/16, 256>>>(b1, ngrp, Wfc, bfc, out);
}

// round 6
// speedup vs baseline: 1.4193x; 1.4193x over previous
#include <cuda_runtime.h>

#define Nn 100000
#define Gg 1000
#define Ee 1600000
#define EGe 16000
#define SCAN_BS 512
#define NB1 ((Nn + SCAN_BS - 1) / SCAN_BS)

// ---------------- scratch (device globals; no runtime allocation) ----------------
static __device__ __align__(16) float g_h1[Nn*128];     // x @ W1
static __device__ __align__(16) float g_xout[Nn*128];   // GAT1 aggregation (pre-bias)
static __device__ __align__(16) float g_asrc1[Nn*4];
static __device__ __align__(16) float g_adst1[Nn*4];
static __device__ __align__(16) float g_h2[Gg*128];
static __device__ __align__(16) float g_xgf[Gg*128];    // GAT2 final (with bias2)
static __device__ __align__(16) float g_adj[Gg*128];    // adjacent-group mean
static __device__ __align__(16) float g_asrc2[Gg*4];
static __device__ __align__(16) float g_adst2[Gg*4];
static __device__ float g_cnt[Gg];

// CSR scratch
static __device__ int g_deg1[Nn];
static __device__ int g_row1[Nn + 1];
static __device__ int g_cur1[Nn];
static __device__ int g_csr1[Ee + Nn];
static __device__ int g_bsum1[NB1];
static __device__ int g_row2[Gg + 1];
static __device__ int g_csr2[EGe + Gg];

__device__ __forceinline__ void redAddV4(float* p, float a, float b, float c, float d) {
    asm volatile("red.global.add.v4.f32 [%0], {%1, %2, %3, %4};"
                 :: "l"(p), "f"(a), "f"(b), "f"(c), "f"(d) : "memory");
}

// ---------------- init: covers Gg*128 = 128000 > Nn ----------------
__global__ void init_kernel() {
    int i = blockIdx.x * blockDim.x + threadIdx.x;
    if (i < Nn) g_deg1[i] = 1;            // self-loop baked into degree
    if (i < Gg*128) g_adj[i] = 0.f;
    if (i < Gg) g_cnt[i] = 0.f;
}

// ---------------- graph-1 CSR build ----------------
__global__ void hist_kernel(const int* __restrict__ dst) {
    int e = blockIdx.x * blockDim.x + threadIdx.x;
    if (e < Ee) atomicAdd(&g_deg1[dst[e]], 1);
}

__global__ void scan1_kernel() {
    __shared__ int s[SCAN_BS];
    int tid = threadIdx.x;
    int i = blockIdx.x * SCAN_BS + tid;
    int v = (i < Nn) ? g_deg1[i] : 0;
    s[tid] = v;
    __syncthreads();
    #pragma unroll
    for (int off = 1; off < SCAN_BS; off <<= 1) {
        int t = (tid >= off) ? s[tid - off] : 0;
        __syncthreads();
        s[tid] += t;
        __syncthreads();
    }
    if (i < Nn) g_row1[i] = s[tid] - v;   // exclusive (within block)
    if (tid == SCAN_BS - 1) g_bsum1[blockIdx.x] = s[tid];
}

__global__ void scan2_kernel() {
    __shared__ int s[256];
    int tid = threadIdx.x;
    int v = (tid < NB1) ? g_bsum1[tid] : 0;
    s[tid] = v;
    __syncthreads();
    #pragma unroll
    for (int off = 1; off < 256; off <<= 1) {
        int t = (tid >= off) ? s[tid - off] : 0;
        __syncthreads();
        s[tid] += t;
        __syncthreads();
    }
    if (tid < NB1) g_bsum1[tid] = s[tid] - v;  // exclusive
}

__global__ void scan3_kernel() {
    int i = blockIdx.x * SCAN_BS + threadIdx.x;
    if (i < Nn) {
        int r = g_row1[i] + g_bsum1[blockIdx.x];
        g_row1[i] = r;
        g_cur1[i] = r;
    }
    if (i == 0) g_row1[Nn] = Ee + Nn;
}

__global__ void scatter_kernel(const int* __restrict__ src, const int* __restrict__ dst) {
    int e = blockIdx.x * blockDim.x + threadIdx.x;
    if (e >= Ee + Nn) return;
    int si, di;
    if (e < Ee) { si = src[e]; di = dst[e]; } else { si = di = e - Ee; }
    int pos = atomicAdd(&g_cur1[di], 1);
    g_csr1[pos] = si;
}

// ---------------- graph-2 CSR build: one block, smem hist+scan+scatter ----------------
__global__ void build_csr2_kernel(const int* __restrict__ eig) {
    __shared__ int sdeg[1024];
    __shared__ int sscan[1024];
    __shared__ int scur[Gg];
    int t = threadIdx.x;
    sdeg[t] = (t < Gg) ? 1 : 0;            // self-loop
    __syncthreads();
    for (int e = t; e < EGe; e += 1024) atomicAdd(&sdeg[eig[EGe + e]], 1);
    __syncthreads();
    int v = sdeg[t];
    sscan[t] = v;
    __syncthreads();
    #pragma unroll
    for (int off = 1; off < 1024; off <<= 1) {
        int tv = (t >= off) ? sscan[t - off] : 0;
        __syncthreads();
        sscan[t] += tv;
        __syncthreads();
    }
    int excl = sscan[t] - v;
    if (t < Gg) { g_row2[t] = excl; scur[t] = excl; }
    if (t == 0) g_row2[Gg] = EGe + Gg;
    __syncthreads();
    for (int e = t; e < EGe + Gg; e += 1024) {
        int si, di;
        if (e < EGe) { si = eig[e]; di = eig[EGe + e]; } else { si = di = e - EGe; }
        int pos = atomicAdd(&scur[di], 1);
        g_csr2[pos] = si;
    }
}

// ---------------- GEMM (plain FFMA, R4-proven): C[n,128] = A @ B, fused att scores ----
__global__ void gemm_k128(const float* __restrict__ A, const float* __restrict__ B,
                          const float* __restrict__ att_s, const float* __restrict__ att_d,
                          int which, int n) {
    float* C   = which ? g_h2 : g_h1;
    float* as_ = which ? g_asrc2 : g_asrc1;
    float* ad_ = which ? g_adst2 : g_adst1;
    __shared__ float As[16][68];   // [k][row], padded
    __shared__ float Bs[16][128];  // [k][col]
    int t = threadIdx.x;
    int rowBase = blockIdx.x * 64;
    int tr = t >> 5, tc = t & 31;
    float acc[8][4];
    #pragma unroll
    for (int i = 0; i < 8; i++)
        #pragma unroll
        for (int j = 0; j < 4; j++) acc[i][j] = 0.f;

    for (int kt = 0; kt < 128; kt += 16) {
        int ar = t >> 2;
        int ac = (t & 3) << 2;
        int row = rowBase + ar;
        float4 av = (row < n) ? *(const float4*)(A + row*128 + kt + ac)
                              : make_float4(0.f, 0.f, 0.f, 0.f);
        As[ac+0][ar] = av.x; As[ac+1][ar] = av.y;
        As[ac+2][ar] = av.z; As[ac+3][ar] = av.w;
        int br = t >> 4;
        int bc = (t & 15) << 3;
        float4 b0 = *(const float4*)(B + (kt + br)*128 + bc);
        float4 b1 = *(const float4*)(B + (kt + br)*128 + bc + 4);
        *(float4*)&Bs[br][bc]     = b0;
        *(float4*)&Bs[br][bc + 4] = b1;
        __syncthreads();
        #pragma unroll
        for (int kk = 0; kk < 16; kk++) {
            float4 a0 = *(const float4*)&As[kk][tr*8];
            float4 a1 = *(const float4*)&As[kk][tr*8 + 4];
            float4 b  = *(const float4*)&Bs[kk][tc*4];
            float av_[8] = {a0.x,a0.y,a0.z,a0.w,a1.x,a1.y,a1.z,a1.w};
            #pragma unroll
            for (int i = 0; i < 8; i++) {
                acc[i][0] += av_[i]*b.x; acc[i][1] += av_[i]*b.y;
                acc[i][2] += av_[i]*b.z; acc[i][3] += av_[i]*b.w;
            }
        }
        __syncthreads();
    }
    float4 sa = *(const float4*)(att_s + tc*4);
    float4 da = *(const float4*)(att_d + tc*4);
    int head = tc >> 3;
    #pragma unroll
    for (int i = 0; i < 8; i++) {
        int row = rowBase + tr*8 + i;
        if (row < n) {
            *(float4*)(C + row*128 + tc*4) =
                make_float4(acc[i][0], acc[i][1], acc[i][2], acc[i][3]);
            float ps = acc[i][0]*sa.x + acc[i][1]*sa.y + acc[i][2]*sa.z + acc[i][3]*sa.w;
            float pd = acc[i][0]*da.x + acc[i][1]*da.y + acc[i][2]*da.z + acc[i][3]*da.w;
            #pragma unroll
            for (int off = 4; off >= 1; off >>= 1) {
                ps += __shfl_xor_sync(0xffffffffu, ps, off);
                pd += __shfl_xor_sync(0xffffffffu, pd, off);
            }
            if ((tc & 7) == 0) {
                as_[row*4 + head] = ps;
                ad_[row*4 + head] = pd;
            }
        }
    }
}

// ---------------- graph-1: fused softmax + aggregation, warp per node, unroll x2 ----
__global__ void csr_agg1_kernel() {
    int gid = blockIdx.x * blockDim.x + threadIdx.x;
    int d = gid >> 5, lane = threadIdx.x & 31;
    if (d >= Nn) return;
    int start = g_row1[d], end = g_row1[d + 1];
    int hd = lane >> 3;
    float adv = __ldg(&g_adst1[d*4 + hd]);
    float4 acc = make_float4(0.f, 0.f, 0.f, 0.f);
    float wsum = 0.f;
    int j = start;
    for (; j + 2 <= end; j += 2) {
        int s0 = __ldg(&g_csr1[j]);
        int s1 = __ldg(&g_csr1[j + 1]);
        float a0 = __ldg(&g_asrc1[s0*4 + hd]);
        float a1 = __ldg(&g_asrc1[s1*4 + hd]);
        float4 h0 = *(const float4*)(g_h1 + s0*128 + lane*4);
        float4 h1 = *(const float4*)(g_h1 + s1*128 + lane*4);
        float e0 = a0 + adv; e0 = e0 > 0.f ? e0 : 0.2f*e0;
        float e1 = a1 + adv; e1 = e1 > 0.f ? e1 : 0.2f*e1;
        float w0 = __expf(e0);
        float w1 = __expf(e1);
        acc.x += w0*h0.x; acc.y += w0*h0.y; acc.z += w0*h0.z; acc.w += w0*h0.w;
        acc.x += w1*h1.x; acc.y += w1*h1.y; acc.z += w1*h1.z; acc.w += w1*h1.w;
        wsum += w0 + w1;
    }
    if (j < end) {
        int s0 = __ldg(&g_csr1[j]);
        float a0 = __ldg(&g_asrc1[s0*4 + hd]);
        float4 h0 = *(const float4*)(g_h1 + s0*128 + lane*4);
        float e0 = a0 + adv; e0 = e0 > 0.f ? e0 : 0.2f*e0;
        float w0 = __expf(e0);
        acc.x += w0*h0.x; acc.y += w0*h0.y; acc.z += w0*h0.z; acc.w += w0*h0.w;
        wsum += w0;
    }
    float inv = 1.f / (wsum + 1e-16f);
    *(float4*)(g_xout + d*128 + lane*4) =
        make_float4(acc.x*inv, acc.y*inv, acc.z*inv, acc.w*inv);
}

// ---------------- graph-2: fused softmax + agg + bias2, writes xgf & d_out tail ----
__global__ void csr_agg2_kernel(const float* __restrict__ bias2, float* __restrict__ dtail) {
    int gid = blockIdx.x * blockDim.x + threadIdx.x;
    int d = gid >> 5, lane = threadIdx.x & 31;
    if (d >= Gg) return;
    int start = g_row2[d], end = g_row2[d + 1];
    int hd = lane >> 3;
    float adv = __ldg(&g_adst2[d*4 + hd]);
    float4 acc = make_float4(0.f, 0.f, 0.f, 0.f);
    float wsum = 0.f;
    for (int j = start; j < end; j++) {
        int si = __ldg(&g_csr2[j]);
        float a = __ldg(&g_asrc2[si*4 + hd]);
        float4 hv = *(const float4*)(g_h2 + si*128 + lane*4);
        float e = a + adv;
        e = e > 0.f ? e : 0.2f*e;
        float w = __expf(e);
        acc.x += w*hv.x; acc.y += w*hv.y; acc.z += w*hv.z; acc.w += w*hv.w;
        wsum += w;
    }
    float inv = 1.f / (wsum + 1e-16f);
    float4 bv = *(const float4*)(bias2 + lane*4);
    float4 r = make_float4(acc.x*inv + bv.x, acc.y*inv + bv.y,
                           acc.z*inv + bv.z, acc.w*inv + bv.w);
    *(float4*)(g_xgf + d*128 + lane*4) = r;
    *(float4*)(dtail + d*128 + lane*4) = r;
}

// ---------------- adjacency mean over group edges ----------------
__global__ void adj_accum_kernel(const int* __restrict__ eg) {
    int gid = blockIdx.x * blockDim.x + threadIdx.x;
    int w = gid >> 5, lane = threadIdx.x & 31;
    if (w >= EGe) return;
    int a = eg[w];         // edge_index_g[0]
    int b = eg[EGe + w];   // edge_index_g[1]
    float4 v = *(const float4*)(g_xgf + b*128 + lane*4);
    redAddV4(g_adj + a*128 + lane*4, v.x, v.y, v.z, v.w);
    if (lane == 0) atomicAdd(&g_cnt[a], 1.f);
}

__global__ void adj_mean_kernel() {
    int i = blockIdx.x * blockDim.x + threadIdx.x;
    if (i < Gg*128) g_adj[i] = g_adj[i] / fmaxf(g_cnt[i >> 7], 1.f);
}

// ---------------- final: bilinear update + FC 128->32 (warp per node, R4-proven) ----
__global__ void final_kernel(const float* __restrict__ bias1, const int* __restrict__ node_group,
                             const float* __restrict__ Wfc, const float* __restrict__ bfc,
                             float* __restrict__ out) {
    __shared__ float Ws[128*32];
    __shared__ float Us[8][128];
    int t = threadIdx.x;
    for (int i = t; i < 128*32; i += 256) Ws[i] = Wfc[i];
    __syncthreads();
    int w = t >> 5, lane = t & 31;
    float4 b1 = *(const float4*)(bias1 + lane*4);
    float bf = bfc[lane];
    for (int j = 0; j < 4; j++) {
        int node = blockIdx.x*32 + w*4 + j;
        if (node < Nn) {
            float4 xo = *(const float4*)(g_xout + node*128 + lane*4);
            xo.x += b1.x; xo.y += b1.y; xo.z += b1.z; xo.w += b1.w;
            int g = node_group[node];
            float4 gf = *(const float4*)(g_xgf + g*128 + lane*4);
            float4 af = *(const float4*)(g_adj + g*128 + lane*4);
            float pg = xo.x*gf.x + xo.y*gf.y + xo.z*gf.z + xo.w*gf.w;
            float pa = xo.x*af.x + xo.y*af.y + xo.z*af.z + xo.w*af.w;
            #pragma unroll
            for (int off = 16; off >= 1; off >>= 1) {
                pg += __shfl_xor_sync(0xffffffffu, pg, off);
                pa += __shfl_xor_sync(0xffffffffu, pa, off);
            }
            float4 u;
            u.x = xo.x + pg*gf.x + pa*af.x;
            u.y = xo.y + pg*gf.y + pa*af.y;
            u.z = xo.z + pg*gf.z + pa*af.z;
            u.w = xo.w + pg*gf.w + pa*af.w;
            *(float4*)&Us[w][lane*4] = u;
            __syncwarp();
            float acc = bf;
            #pragma unroll
            for (int k = 0; k < 128; k++) acc += Us[w][k] * Ws[k*32 + lane];
            out[node*32 + lane] = acc;
            __syncwarp();
        }
    }
}

// ---------------- launch ----------------
extern "C" void kernel_launch(void* const* d_in, const int* in_sizes, int n_in,
                              void* d_out, int out_size) {
    const float* x    = (const float*)d_in[0];
    const float* x_g  = (const float*)d_in[1];
    const int*   ei   = (const int*)d_in[2];
    const int*   eig  = (const int*)d_in[3];
    const int*   ngrp = (const int*)d_in[4];
    const float* W1   = (const float*)d_in[5];
    const float* as1  = (const float*)d_in[6];
    const float* ad1  = (const float*)d_in[7];
    const float* b1   = (const float*)d_in[8];
    const float* W2   = (const float*)d_in[9];
    const float* as2  = (const float*)d_in[10];
    const float* ad2  = (const float*)d_in[11];
    const float* b2   = (const float*)d_in[12];
    const float* Wfc  = (const float*)d_in[13];
    const float* bfc  = (const float*)d_in[14];
    float* out = (float*)d_out;

    init_kernel<<<(Gg*128 + 255)/256, 256>>>();

    // CSR builds
    hist_kernel<<<(Ee + 255)/256, 256>>>(ei + Ee);
    scan1_kernel<<<NB1, SCAN_BS>>>();
    scan2_kernel<<<1, 256>>>();
    scan3_kernel<<<NB1, SCAN_BS>>>();
    scatter_kernel<<<(Ee + Nn + 255)/256, 256>>>(ei, ei + Ee);
    build_csr2_kernel<<<1, 1024>>>(eig);

    // group-graph chain (small)
    gemm_k128<<<(Gg + 63)/64, 256>>>(x_g, W2, as2, ad2, 1, Gg);
    csr_agg2_kernel<<<(Gg*32 + 255)/256, 256>>>(b2, out + Nn*32);
    adj_accum_kernel<<<(EGe*32 + 255)/256, 256>>>(eig);
    adj_mean_kernel<<<(Gg*128 + 255)/256, 256>>>();

    // big-graph chain
    gemm_k128<<<(Nn + 63)/64, 256>>>(x, W1, as1, ad1, 0, Nn);
    csr_agg1_kernel<<<(Nn*32 + 255)/256, 256>>>();
    final_kernel<<<(Nn + 31)/32, 256>>>(b1, ngrp, Wfc, bfc, out);
}

// round 7
// speedup vs baseline: 1.4487x; 1.0207x over previous
#include <cuda_runtime.h>

#define Nn 100000
#define Gg 1000
#define Ee 1600000
#define EGe 16000
#define SCAN_BS 512
#define NB1 ((Nn + SCAN_BS - 1) / SCAN_BS)

// ---------------- scratch (device globals; no runtime allocation) ----------------
static __device__ __align__(16) float g_h1[Nn*128];     // x @ W1
static __device__ __align__(16) float g_asrc1[Nn*4];
static __device__ __align__(16) float g_adst1[Nn*4];
static __device__ __align__(16) float g_h2[Gg*128];
static __device__ __align__(16) float g_xgf[Gg*128];    // GAT2 final (with bias2)
static __device__ __align__(16) float g_adj[Gg*128];    // adjacent-group mean
static __device__ __align__(16) float g_asrc2[Gg*4];
static __device__ __align__(16) float g_adst2[Gg*4];
static __device__ float g_cnt[Gg];

// CSR scratch
static __device__ int g_deg1[Nn];
static __device__ int g_row1[Nn + 1];
static __device__ int g_cur1[Nn];
static __device__ int g_csr1[Ee + Nn];
static __device__ int g_bsum1[NB1];
static __device__ int g_row2[Gg + 1];
static __device__ int g_csr2[EGe + Gg];

__device__ __forceinline__ void redAddV4(float* p, float a, float b, float c, float d) {
    asm volatile("red.global.add.v4.f32 [%0], {%1, %2, %3, %4};"
                 :: "l"(p), "f"(a), "f"(b), "f"(c), "f"(d) : "memory");
}

// ---------------- init: covers Gg*128 = 128000 > Nn ----------------
__global__ void init_kernel() {
    int i = blockIdx.x * blockDim.x + threadIdx.x;
    if (i < Nn) g_deg1[i] = 1;            // self-loop baked into degree
    if (i < Gg*128) g_adj[i] = 0.f;
    if (i < Gg) g_cnt[i] = 0.f;
}

// ---------------- graph-1 CSR build ----------------
__global__ void hist_kernel(const int* __restrict__ dst) {
    int e = blockIdx.x * blockDim.x + threadIdx.x;
    if (e < Ee) atomicAdd(&g_deg1[dst[e]], 1);
}

__global__ void scan1_kernel() {
    __shared__ int s[SCAN_BS];
    int tid = threadIdx.x;
    int i = blockIdx.x * SCAN_BS + tid;
    int v = (i < Nn) ? g_deg1[i] : 0;
    s[tid] = v;
    __syncthreads();
    #pragma unroll
    for (int off = 1; off < SCAN_BS; off <<= 1) {
        int t = (tid >= off) ? s[tid - off] : 0;
        __syncthreads();
        s[tid] += t;
        __syncthreads();
    }
    if (i < Nn) g_row1[i] = s[tid] - v;   // exclusive (within block)
    if (tid == SCAN_BS - 1) g_bsum1[blockIdx.x] = s[tid];
}

__global__ void scan2_kernel() {
    __shared__ int s[256];
    int tid = threadIdx.x;
    int v = (tid < NB1) ? g_bsum1[tid] : 0;
    s[tid] = v;
    __syncthreads();
    #pragma unroll
    for (int off = 1; off < 256; off <<= 1) {
        int t = (tid >= off) ? s[tid - off] : 0;
        __syncthreads();
        s[tid] += t;
        __syncthreads();
    }
    if (tid < NB1) g_bsum1[tid] = s[tid] - v;  // exclusive
}

__global__ void scan3_kernel() {
    int i = blockIdx.x * SCAN_BS + threadIdx.x;
    if (i < Nn) {
        int r = g_row1[i] + g_bsum1[blockIdx.x];
        g_row1[i] = r;
        g_cur1[i] = r;
    }
    if (i == 0) g_row1[Nn] = Ee + Nn;
}

__global__ void scatter_kernel(const int* __restrict__ src, const int* __restrict__ dst) {
    int e = blockIdx.x * blockDim.x + threadIdx.x;
    if (e >= Ee + Nn) return;
    int si, di;
    if (e < Ee) { si = src[e]; di = dst[e]; } else { si = di = e - Ee; }
    int pos = atomicAdd(&g_cur1[di], 1);
    g_csr1[pos] = si;
}

// ---------------- graph-2 CSR build: one block, smem hist+scan+scatter ----------------
__global__ void build_csr2_kernel(const int* __restrict__ eig) {
    __shared__ int sdeg[1024];
    __shared__ int sscan[1024];
    __shared__ int scur[Gg];
    int t = threadIdx.x;
    sdeg[t] = (t < Gg) ? 1 : 0;            // self-loop
    __syncthreads();
    for (int e = t; e < EGe; e += 1024) atomicAdd(&sdeg[eig[EGe + e]], 1);
    __syncthreads();
    int v = sdeg[t];
    sscan[t] = v;
    __syncthreads();
    #pragma unroll
    for (int off = 1; off < 1024; off <<= 1) {
        int tv = (t >= off) ? sscan[t - off] : 0;
        __syncthreads();
        sscan[t] += tv;
        __syncthreads();
    }
    int excl = sscan[t] - v;
    if (t < Gg) { g_row2[t] = excl; scur[t] = excl; }
    if (t == 0) g_row2[Gg] = EGe + Gg;
    __syncthreads();
    for (int e = t; e < EGe + Gg; e += 1024) {
        int si, di;
        if (e < EGe) { si = eig[e]; di = eig[EGe + e]; } else { si = di = e - EGe; }
        int pos = atomicAdd(&scur[di], 1);
        g_csr2[pos] = si;
    }
}

// ---------------- GEMM (plain FFMA, R4-proven): C[n,128] = A @ B, fused att scores ----
__global__ void gemm_k128(const float* __restrict__ A, const float* __restrict__ B,
                          const float* __restrict__ att_s, const float* __restrict__ att_d,
                          int which, int n) {
    float* C   = which ? g_h2 : g_h1;
    float* as_ = which ? g_asrc2 : g_asrc1;
    float* ad_ = which ? g_adst2 : g_adst1;
    __shared__ float As[16][68];   // [k][row], padded
    __shared__ float Bs[16][128];  // [k][col]
    int t = threadIdx.x;
    int rowBase = blockIdx.x * 64;
    int tr = t >> 5, tc = t & 31;
    float acc[8][4];
    #pragma unroll
    for (int i = 0; i < 8; i++)
        #pragma unroll
        for (int j = 0; j < 4; j++) acc[i][j] = 0.f;

    for (int kt = 0; kt < 128; kt += 16) {
        int ar = t >> 2;
        int ac = (t & 3) << 2;
        int row = rowBase + ar;
        float4 av = (row < n) ? *(const float4*)(A + row*128 + kt + ac)
                              : make_float4(0.f, 0.f, 0.f, 0.f);
        As[ac+0][ar] = av.x; As[ac+1][ar] = av.y;
        As[ac+2][ar] = av.z; As[ac+3][ar] = av.w;
        int br = t >> 4;
        int bc = (t & 15) << 3;
        float4 b0 = *(const float4*)(B + (kt + br)*128 + bc);
        float4 b1 = *(const float4*)(B + (kt + br)*128 + bc + 4);
        *(float4*)&Bs[br][bc]     = b0;
        *(float4*)&Bs[br][bc + 4] = b1;
        __syncthreads();
        #pragma unroll
        for (int kk = 0; kk < 16; kk++) {
            float4 a0 = *(const float4*)&As[kk][tr*8];
            float4 a1 = *(const float4*)&As[kk][tr*8 + 4];
            float4 b  = *(const float4*)&Bs[kk][tc*4];
            float av_[8] = {a0.x,a0.y,a0.z,a0.w,a1.x,a1.y,a1.z,a1.w};
            #pragma unroll
            for (int i = 0; i < 8; i++) {
                acc[i][0] += av_[i]*b.x; acc[i][1] += av_[i]*b.y;
                acc[i][2] += av_[i]*b.z; acc[i][3] += av_[i]*b.w;
            }
        }
        __syncthreads();
    }
    float4 sa = *(const float4*)(att_s + tc*4);
    float4 da = *(const float4*)(att_d + tc*4);
    int head = tc >> 3;
    #pragma unroll
    for (int i = 0; i < 8; i++) {
        int row = rowBase + tr*8 + i;
        if (row < n) {
            *(float4*)(C + row*128 + tc*4) =
                make_float4(acc[i][0], acc[i][1], acc[i][2], acc[i][3]);
            float ps = acc[i][0]*sa.x + acc[i][1]*sa.y + acc[i][2]*sa.z + acc[i][3]*sa.w;
            float pd = acc[i][0]*da.x + acc[i][1]*da.y + acc[i][2]*da.z + acc[i][3]*da.w;
            #pragma unroll
            for (int off = 4; off >= 1; off >>= 1) {
                ps += __shfl_xor_sync(0xffffffffu, ps, off);
                pd += __shfl_xor_sync(0xffffffffu, pd, off);
            }
            if ((tc & 7) == 0) {
                as_[row*4 + head] = ps;
                ad_[row*4 + head] = pd;
            }
        }
    }
}

// ---------------- graph-1: fused agg + bias + bilinear + FC, warp per node --------
// 8 warps/block, 8 nodes/block, NO __syncthreads after weight preload: each warp
// runs its own gather loop then its private FC using only __syncwarp (no stragglers).
__global__ void csr_agg1_final_kernel(const float* __restrict__ bias1,
                                      const int* __restrict__ node_group,
                                      const float* __restrict__ Wfc,
                                      const float* __restrict__ bfc,
                                      float* __restrict__ out) {
    __shared__ float Ws[128*32];
    __shared__ float Us[8][128];
    int t = threadIdx.x;
    for (int i = t; i < 128*32; i += 256) Ws[i] = Wfc[i];
    __syncthreads();              // only sync: after uniform weight preload

    int w = t >> 5, lane = t & 31;
    int d = blockIdx.x*8 + w;     // Nn % 8 == 0 -> always valid
    int start = g_row1[d], end = g_row1[d + 1];
    int hd = lane >> 3;
    float adv = __ldg(&g_adst1[d*4 + hd]);
    float4 acc = make_float4(0.f, 0.f, 0.f, 0.f);
    float wsum = 0.f;

    int j = start;
    for (; j + 4 <= end; j += 4) {          // 4 gathers in flight (MLP=4)
        int s0 = __ldg(&g_csr1[j]);
        int s1 = __ldg(&g_csr1[j + 1]);
        int s2 = __ldg(&g_csr1[j + 2]);
        int s3 = __ldg(&g_csr1[j + 3]);
        float a0 = __ldg(&g_asrc1[s0*4 + hd]);
        float a1 = __ldg(&g_asrc1[s1*4 + hd]);
        float a2 = __ldg(&g_asrc1[s2*4 + hd]);
        float a3 = __ldg(&g_asrc1[s3*4 + hd]);
        float4 h0 = *(const float4*)(g_h1 + s0*128 + lane*4);
        float4 h1 = *(const float4*)(g_h1 + s1*128 + lane*4);
        float4 h2 = *(const float4*)(g_h1 + s2*128 + lane*4);
        float4 h3 = *(const float4*)(g_h1 + s3*128 + lane*4);
        float e0 = a0 + adv; e0 = e0 > 0.f ? e0 : 0.2f*e0;
        float e1 = a1 + adv; e1 = e1 > 0.f ? e1 : 0.2f*e1;
        float e2 = a2 + adv; e2 = e2 > 0.f ? e2 : 0.2f*e2;
        float e3 = a3 + adv; e3 = e3 > 0.f ? e3 : 0.2f*e3;
        float w0 = __expf(e0), w1 = __expf(e1), w2 = __expf(e2), w3 = __expf(e3);
        acc.x += w0*h0.x + w1*h1.x + w2*h2.x + w3*h3.x;
        acc.y += w0*h0.y + w1*h1.y + w2*h2.y + w3*h3.y;
        acc.z += w0*h0.z + w1*h1.z + w2*h2.z + w3*h3.z;
        acc.w += w0*h0.w + w1*h1.w + w2*h2.w + w3*h3.w;
        wsum += (w0 + w1) + (w2 + w3);
    }
    for (; j < end; j++) {
        int s0 = __ldg(&g_csr1[j]);
        float a0 = __ldg(&g_asrc1[s0*4 + hd]);
        float4 h0 = *(const float4*)(g_h1 + s0*128 + lane*4);
        float e0 = a0 + adv; e0 = e0 > 0.f ? e0 : 0.2f*e0;
        float w0 = __expf(e0);
        acc.x += w0*h0.x; acc.y += w0*h0.y; acc.z += w0*h0.z; acc.w += w0*h0.w;
        wsum += w0;
    }

    float inv = 1.f / (wsum + 1e-16f);
    float4 b1 = *(const float4*)(bias1 + lane*4);
    float4 xo = make_float4(acc.x*inv + b1.x, acc.y*inv + b1.y,
                            acc.z*inv + b1.z, acc.w*inv + b1.w);
    int g = __ldg(&node_group[d]);
    float4 gf = *(const float4*)(g_xgf + g*128 + lane*4);
    float4 af = *(const float4*)(g_adj + g*128 + lane*4);
    float pg = xo.x*gf.x + xo.y*gf.y + xo.z*gf.z + xo.w*gf.w;
    float pa = xo.x*af.x + xo.y*af.y + xo.z*af.z + xo.w*af.w;
    #pragma unroll
    for (int off = 16; off >= 1; off >>= 1) {
        pg += __shfl_xor_sync(0xffffffffu, pg, off);
        pa += __shfl_xor_sync(0xffffffffu, pa, off);
    }
    float4 u;
    u.x = xo.x + pg*gf.x + pa*af.x;
    u.y = xo.y + pg*gf.y + pa*af.y;
    u.z = xo.z + pg*gf.z + pa*af.z;
    u.w = xo.w + pg*gf.w + pa*af.w;
    *(float4*)&Us[w][lane*4] = u;
    __syncwarp();
    float accO = bfc[lane];
    #pragma unroll
    for (int k = 0; k < 128; k++) accO += Us[w][k] * Ws[k*32 + lane];
    out[d*32 + lane] = accO;
}

// ---------------- graph-2: fused softmax + agg + bias2, writes xgf & d_out tail ----
__global__ void csr_agg2_kernel(const float* __restrict__ bias2, float* __restrict__ dtail) {
    int gid = blockIdx.x * blockDim.x + threadIdx.x;
    int d = gid >> 5, lane = threadIdx.x & 31;
    if (d >= Gg) return;
    int start = g_row2[d], end = g_row2[d + 1];
    int hd = lane >> 3;
    float adv = __ldg(&g_adst2[d*4 + hd]);
    float4 acc = make_float4(0.f, 0.f, 0.f, 0.f);
    float wsum = 0.f;
    for (int j = start; j < end; j++) {
        int si = __ldg(&g_csr2[j]);
        float a = __ldg(&g_asrc2[si*4 + hd]);
        float4 hv = *(const float4*)(g_h2 + si*128 + lane*4);
        float e = a + adv;
        e = e > 0.f ? e : 0.2f*e;
        float w = __expf(e);
        acc.x += w*hv.x; acc.y += w*hv.y; acc.z += w*hv.z; acc.w += w*hv.w;
        wsum += w;
    }
    float inv = 1.f / (wsum + 1e-16f);
    float4 bv = *(const float4*)(bias2 + lane*4);
    float4 r = make_float4(acc.x*inv + bv.x, acc.y*inv + bv.y,
                           acc.z*inv + bv.z, acc.w*inv + bv.w);
    *(float4*)(g_xgf + d*128 + lane*4) = r;
    *(float4*)(dtail + d*128 + lane*4) = r;
}

// ---------------- adjacency mean over group edges ----------------
__global__ void adj_accum_kernel(const int* __restrict__ eg) {
    int gid = blockIdx.x * blockDim.x + threadIdx.x;
    int w = gid >> 5, lane = threadIdx.x & 31;
    if (w >= EGe) return;
    int a = eg[w];         // edge_index_g[0]
    int b = eg[EGe + w];   // edge_index_g[1]
    float4 v = *(const float4*)(g_xgf + b*128 + lane*4);
    redAddV4(g_adj + a*128 + lane*4, v.x, v.y, v.z, v.w);
    if (lane == 0) atomicAdd(&g_cnt[a], 1.f);
}

__global__ void adj_mean_kernel() {
    int i = blockIdx.x * blockDim.x + threadIdx.x;
    if (i < Gg*128) g_adj[i] = g_adj[i] / fmaxf(g_cnt[i >> 7], 1.f);
}

// ---------------- launch ----------------
extern "C" void kernel_launch(void* const* d_in, const int* in_sizes, int n_in,
                              void* d_out, int out_size) {
    const float* x    = (const float*)d_in[0];
    const float* x_g  = (const float*)d_in[1];
    const int*   ei   = (const int*)d_in[2];
    const int*   eig  = (const int*)d_in[3];
    const int*   ngrp = (const int*)d_in[4];
    const float* W1   = (const float*)d_in[5];
    const float* as1  = (const float*)d_in[6];
    const float* ad1  = (const float*)d_in[7];
    const float* b1   = (const float*)d_in[8];
    const float* W2   = (const float*)d_in[9];
    const float* as2  = (const float*)d_in[10];
    const float* ad2  = (const float*)d_in[11];
    const float* b2   = (const float*)d_in[12];
    const float* Wfc  = (const float*)d_in[13];
    const float* bfc  = (const float*)d_in[14];
    float* out = (float*)d_out;

    init_kernel<<<(Gg*128 + 255)/256, 256>>>();

    // CSR builds
    hist_kernel<<<(Ee + 255)/256, 256>>>(ei + Ee);
    scan1_kernel<<<NB1, SCAN_BS>>>();
    scan2_kernel<<<1, 256>>>();
    scan3_kernel<<<NB1, SCAN_BS>>>();
    scatter_kernel<<<(Ee + Nn + 255)/256, 256>>>(ei, ei + Ee);
    build_csr2_kernel<<<1, 1024>>>(eig);

    // group-graph chain (small)
    gemm_k128<<<(Gg + 63)/64, 256>>>(x_g, W2, as2, ad2, 1, Gg);
    csr_agg2_kernel<<<(Gg*32 + 255)/256, 256>>>(b2, out + Nn*32);
    adj_accum_kernel<<<(EGe*32 + 255)/256, 256>>>(eig);
    adj_mean_kernel<<<(Gg*128 + 255)/256, 256>>>();

    // big-graph chain (agg + final fully fused, atomic-free, no xout round-trip)
    gemm_k128<<<(Nn + 63)/64, 256>>>(x, W1, as1, ad1, 0, Nn);
    csr_agg1_final_kernel<<<Nn/8, 256>>>(b1, ngrp, Wfc, bfc, out);
}